// round 3
// baseline (speedup 1.0000x reference)
#include <cuda_runtime.h>

// dims
#define NW   8192
#define LMAX 16
#define WED  506
#define WHD  512
#define G4   2048   // 4*WHD
#define CED  6
#define CHD  6
#define TLS  64

// ---------------- device scratch (no allocations allowed) ----------------
__device__ float g_hchar[NW * CHD];
__device__ float g_xp[(size_t)NW * G4];      // 64 MB
__device__ float g_hs[(size_t)NW * WHD];     // 16 MB
__device__ unsigned long long g_hbuf[2 * WHD];

__device__ __forceinline__ float sigm(float x)  { return 1.f / (1.f + __expf(-x)); }
__device__ __forceinline__ float tanh_(float x) { return 2.f / (1.f + __expf(-2.f * x)) - 1.f; }

// packed fp32x2 FMA (Blackwell; ptxas never emits FFMA2 from C++)
__device__ __forceinline__ unsigned long long ffma2(unsigned long long a,
                                                    unsigned long long b,
                                                    unsigned long long c) {
    unsigned long long d;
    asm("fma.rn.f32x2 %0, %1, %2, %3;" : "=l"(d) : "l"(a), "l"(b), "l"(c));
    return d;
}
__device__ __forceinline__ float unpack_add(unsigned long long a) {
    return __uint_as_float((unsigned)a) + __uint_as_float((unsigned)(a >> 32));
}

// ---------------- init: reset tag buffers (tags monotone within a run) ----
__global__ void init_kernel() {
    int i = blockIdx.x * blockDim.x + threadIdx.x;
    if (i < 2 * WHD) g_hbuf[i] = 0ull;   // tag=0, value=0.0f  (h_0 = 0)
}

// ---------------- char-level LSTM: one thread per word ----------------
__global__ void char_lstm_kernel(const int* __restrict__ chars,
                                 const int* __restrict__ lens,
                                 const float* __restrict__ cemb,   // [128,6]
                                 const float* __restrict__ cWih,   // [24,6]
                                 const float* __restrict__ cWhh,   // [24,6]
                                 const float* __restrict__ cb) {   // [24]
    __shared__ float sE[128 * CED];
    __shared__ float sWi[24 * CED];
    __shared__ float sWh[24 * CHD];
    __shared__ float sB[24];
    int tid = threadIdx.x;
    for (int i = tid; i < 128 * CED; i += blockDim.x) sE[i] = cemb[i];
    if (tid < 144) { sWi[tid] = cWih[tid]; sWh[tid] = cWhh[tid]; }
    if (tid < 24) sB[tid] = cb[tid];
    __syncthreads();

    int n = blockIdx.x * blockDim.x + tid;
    if (n >= NW) return;
    int len = lens[n];
    float h[CHD], cs[CHD];
#pragma unroll
    for (int i = 0; i < CHD; i++) { h[i] = 0.f; cs[i] = 0.f; }

    for (int l = 0; l < len; l++) {
        int ch = chars[n * LMAX + l];
        const float* e = &sE[ch * CED];
        float x0 = e[0], x1 = e[1], x2 = e[2], x3 = e[3], x4 = e[4], x5 = e[5];
        float pre[24];
#pragma unroll
        for (int gi = 0; gi < 24; gi++) {
            const float* wi = &sWi[gi * CED];
            const float* wh = &sWh[gi * CHD];
            float p = sB[gi];
            p = fmaf(wi[0], x0, p); p = fmaf(wi[1], x1, p); p = fmaf(wi[2], x2, p);
            p = fmaf(wi[3], x3, p); p = fmaf(wi[4], x4, p); p = fmaf(wi[5], x5, p);
            p = fmaf(wh[0], h[0], p); p = fmaf(wh[1], h[1], p); p = fmaf(wh[2], h[2], p);
            p = fmaf(wh[3], h[3], p); p = fmaf(wh[4], h[4], p); p = fmaf(wh[5], h[5], p);
            pre[gi] = p;
        }
#pragma unroll
        for (int hd = 0; hd < CHD; hd++) {
            float ig = sigm(pre[hd]);
            float fg = sigm(pre[CHD + hd]);
            float gg = tanh_(pre[2 * CHD + hd]);
            float og = sigm(pre[3 * CHD + hd]);
            cs[hd] = fg * cs[hd] + ig * gg;
            h[hd]  = og * tanh_(cs[hd]);
        }
    }
#pragma unroll
    for (int hd = 0; hd < CHD; hd++) g_hchar[n * CHD + hd] = h[hd];
}

// ---------------- xp GEMM: xp[n, r] = dot(x[n,:], Wih[r,:]) + b[r] ----------
#define BM 64
#define BN 64
#define BK 32
__global__ void xp_gemm_kernel(const int* __restrict__ words,
                               const float* __restrict__ wemb,   // [50000,506]
                               const float* __restrict__ Wih,    // [2048,512]
                               const float* __restrict__ wb) {   // [2048]
    __shared__ float As[BK][BM + 4];
    __shared__ float Bs[BK][BN + 4];
    __shared__ int widx[BM];

    int bn = blockIdx.x;
    int bm = blockIdx.y;
    int tid = threadIdx.x;

    if (tid < BM) widx[tid] = words[bm * BM + tid];
    __syncthreads();

    int tx = tid % 16, ty = tid / 16;
    int lm = tid % 64;
    int lk = (tid / 64) * 8;

    float acc[4][4];
#pragma unroll
    for (int i = 0; i < 4; i++)
#pragma unroll
        for (int j = 0; j < 4; j++) acc[i][j] = 0.f;

    int m_g = bm * BM + lm;
    const float* arow = wemb + (size_t)widx[lm] * WED;
    const float* brow = Wih + (size_t)(bn * BN + lm) * WHD;

    for (int k0 = 0; k0 < WHD; k0 += BK) {
#pragma unroll
        for (int q = 0; q < 8; q++) {
            int k = k0 + lk + q;
            float v = (k < WED) ? arow[k] : g_hchar[m_g * CHD + (k - WED)];
            As[lk + q][lm] = v;
            Bs[lk + q][lm] = brow[k];
        }
        __syncthreads();
#pragma unroll
        for (int k = 0; k < BK; k++) {
            float4 a = *(const float4*)&As[k][ty * 4];
            float4 b = *(const float4*)&Bs[k][tx * 4];
            acc[0][0] = fmaf(a.x, b.x, acc[0][0]); acc[0][1] = fmaf(a.x, b.y, acc[0][1]);
            acc[0][2] = fmaf(a.x, b.z, acc[0][2]); acc[0][3] = fmaf(a.x, b.w, acc[0][3]);
            acc[1][0] = fmaf(a.y, b.x, acc[1][0]); acc[1][1] = fmaf(a.y, b.y, acc[1][1]);
            acc[1][2] = fmaf(a.y, b.z, acc[1][2]); acc[1][3] = fmaf(a.y, b.w, acc[1][3]);
            acc[2][0] = fmaf(a.z, b.x, acc[2][0]); acc[2][1] = fmaf(a.z, b.y, acc[2][1]);
            acc[2][2] = fmaf(a.z, b.z, acc[2][2]); acc[2][3] = fmaf(a.z, b.w, acc[2][3]);
            acc[3][0] = fmaf(a.w, b.x, acc[3][0]); acc[3][1] = fmaf(a.w, b.y, acc[3][1]);
            acc[3][2] = fmaf(a.w, b.z, acc[3][2]); acc[3][3] = fmaf(a.w, b.w, acc[3][3]);
        }
        __syncthreads();
    }
#pragma unroll
    for (int i = 0; i < 4; i++) {
        int m = bm * BM + ty * 4 + i;
#pragma unroll
        for (int j = 0; j < 4; j++) {
            int n = bn * BN + tx * 4 + j;
            g_xp[(size_t)m * G4 + n] = acc[i][j] + wb[n];
        }
    }
}

// ---------------- persistent word LSTM (warp-per-hidden-unit) ----------------
// 128 blocks x 128 threads. Warp w of block b owns hidden unit j = 4b + w.
// Lane l covers columns [16l, 16l+16) for all 4 gate rows (g*512 + j).
// Weights in registers as packed f32x2; matvec via FFMA2.
// h exchange: (tag<<32 | float_bits) u64, double-buffered by parity; 128
// threads stage 4 u64 each into double-buffered smem; ONE barrier per step.
#define WBLK 128
#define WTHR 128
#define PFD  4     // xp prefetch distance (steps), register ring via unroll-4
__global__ void __launch_bounds__(WTHR, 1)
word_lstm_kernel(const float* __restrict__ Whh) {  // [2048,512]
    int b = blockIdx.x, t = threadIdx.x;
    int w = t >> 5;          // warp -> local unit
    int lane = t & 31;
    int j = 4 * b + w;       // global hidden unit

    // weight registers: wreg[g][c] = packed cols (16*lane + 2c, +1) of row g*512+j
    unsigned long long wreg[4][8];
#pragma unroll
    for (int g = 0; g < 4; g++) {
        const ulonglong2* wr =
            (const ulonglong2*)(Whh + (size_t)(g * WHD + j) * WHD);
#pragma unroll
        for (int c4 = 0; c4 < 4; c4++) {
            ulonglong2 u = wr[lane * 4 + c4];
            wreg[g][2 * c4]     = u.x;
            wreg[g][2 * c4 + 1] = u.y;
        }
    }

    __shared__ __align__(16) float h_s[2][WHD];

    // xp rows this lane consumes (lanes 0..3 only): row = lane*512 + j
    const float* xprow = g_xp + (size_t)(lane < 4 ? lane : 0) * WHD + j;
    bool xact = (lane < 4);
    // preload xp for steps 1..4
    float v0 = xact ? __ldcg(&xprow[(size_t)0 * G4]) : 0.f;
    float v1 = xact ? __ldcg(&xprow[(size_t)1 * G4]) : 0.f;
    float v2 = xact ? __ldcg(&xprow[(size_t)2 * G4]) : 0.f;
    float v3 = xact ? __ldcg(&xprow[(size_t)3 * G4]) : 0.f;

    float cst = 0.f;

#define LSTM_STEP(S, XPV)                                                      \
    {                                                                          \
        int par = (S - 1) & 1;                                                 \
        /* poll + stage: thread t brings units 4t..4t+3 */                     \
        {                                                                      \
            unsigned long long tg = (unsigned long long)(S - 1);               \
            volatile unsigned long long* src = g_hbuf + par * WHD + 4 * t;     \
            unsigned long long q0, q1, q2, q3;                                 \
            do {                                                               \
                q0 = src[0]; q1 = src[1]; q2 = src[2]; q3 = src[3];            \
            } while (((q0 >> 32) != tg) | ((q1 >> 32) != tg) |                 \
                     ((q2 >> 32) != tg) | ((q3 >> 32) != tg));                 \
            float4 hv = make_float4(__uint_as_float((unsigned)q0),             \
                                    __uint_as_float((unsigned)q1),             \
                                    __uint_as_float((unsigned)q2),             \
                                    __uint_as_float((unsigned)q3));            \
            *(float4*)&h_s[par][4 * t] = hv;                                   \
        }                                                                      \
        __syncthreads();                                                       \
        /* matvec: 4 gates x 16 cols per lane, packed f32x2 */                 \
        const ulonglong2* hp = (const ulonglong2*)&h_s[par][0];                \
        unsigned long long a0 = 0, a1 = 0, a2 = 0, a3 = 0;                     \
        _Pragma("unroll")                                                      \
        for (int c4 = 0; c4 < 4; c4++) {                                       \
            ulonglong2 hu = hp[lane * 4 + c4];                                 \
            a0 = ffma2(wreg[0][2 * c4], hu.x, a0);                             \
            a1 = ffma2(wreg[1][2 * c4], hu.x, a1);                             \
            a2 = ffma2(wreg[2][2 * c4], hu.x, a2);                             \
            a3 = ffma2(wreg[3][2 * c4], hu.x, a3);                             \
            a0 = ffma2(wreg[0][2 * c4 + 1], hu.y, a0);                         \
            a1 = ffma2(wreg[1][2 * c4 + 1], hu.y, a1);                         \
            a2 = ffma2(wreg[2][2 * c4 + 1], hu.y, a2);                         \
            a3 = ffma2(wreg[3][2 * c4 + 1], hu.y, a3);                         \
        }                                                                      \
        float s0 = unpack_add(a0), s1 = unpack_add(a1);                        \
        float s2 = unpack_add(a2), s3 = unpack_add(a3);                        \
        _Pragma("unroll")                                                      \
        for (int d = 16; d >= 1; d >>= 1) {                                    \
            s0 += __shfl_xor_sync(0xffffffffu, s0, d);                         \
            s1 += __shfl_xor_sync(0xffffffffu, s1, d);                         \
            s2 += __shfl_xor_sync(0xffffffffu, s2, d);                         \
            s3 += __shfl_xor_sync(0xffffffffu, s3, d);                         \
        }                                                                      \
        /* lanes 0..3 apply gate nonlinearities in parallel */                 \
        float pre = (lane == 0 ? s0 : lane == 1 ? s1 : lane == 2 ? s2 : s3)    \
                    + (XPV);                                                   \
        float nl = (lane == 2) ? tanh_(pre) : sigm(pre);                       \
        float ig = __shfl_sync(0xffffffffu, nl, 0);                            \
        float fg = __shfl_sync(0xffffffffu, nl, 1);                            \
        float gv = __shfl_sync(0xffffffffu, nl, 2);                            \
        float og = __shfl_sync(0xffffffffu, nl, 3);                            \
        cst = fg * cst + ig * gv;                                              \
        float hval = og * tanh_(cst);                                          \
        if (lane == 0) {                                                       \
            g_hs[(size_t)(S - 1) * WHD + j] = hval;                            \
            unsigned long long pk = ((unsigned long long)(S) << 32) |          \
                                    (unsigned long long)__float_as_uint(hval); \
            ((volatile unsigned long long*)g_hbuf)[(S & 1) * WHD + j] = pk;    \
        }                                                                      \
    }

    for (int s = 1; s <= NW; s += 4) {
        LSTM_STEP(s, v0);
        if (xact && s + 4 <= NW) v0 = __ldcg(&xprow[(size_t)(s + 3) * G4]);
        LSTM_STEP(s + 1, v1);
        if (xact && s + 5 <= NW) v1 = __ldcg(&xprow[(size_t)(s + 4) * G4]);
        LSTM_STEP(s + 2, v2);
        if (xact && s + 6 <= NW) v2 = __ldcg(&xprow[(size_t)(s + 5) * G4]);
        LSTM_STEP(s + 3, v3);
        if (xact && s + 7 <= NW) v3 = __ldcg(&xprow[(size_t)(s + 6) * G4]);
    }
#undef LSTM_STEP
}

// ---------------- logits + log_softmax: one block (64 threads) per row ----
__global__ void logits_kernel(const float* __restrict__ outW,  // [64,512]
                              const float* __restrict__ outb,  // [64]
                              float* __restrict__ out) {       // [8192,64]
    int row = blockIdx.x;
    int t = threadIdx.x;          // 0..63 (tag)
    __shared__ float h_s[WHD];
    __shared__ float sm_[2], ss_[2];

    for (int i = t; i < WHD; i += 64) h_s[i] = g_hs[(size_t)row * WHD + i];
    __syncthreads();

    float acc = outb[t];
    const float4* w4 = (const float4*)(outW + (size_t)t * WHD);
#pragma unroll 8
    for (int k4 = 0; k4 < WHD / 4; k4++) {
        float4 wv = __ldg(&w4[k4]);
        acc = fmaf(wv.x, h_s[k4 * 4 + 0], acc);
        acc = fmaf(wv.y, h_s[k4 * 4 + 1], acc);
        acc = fmaf(wv.z, h_s[k4 * 4 + 2], acc);
        acc = fmaf(wv.w, h_s[k4 * 4 + 3], acc);
    }
    int lane = t & 31, wp = t >> 5;
    float m = acc;
#pragma unroll
    for (int d = 16; d >= 1; d >>= 1) m = fmaxf(m, __shfl_xor_sync(0xffffffffu, m, d));
    if (lane == 0) sm_[wp] = m;
    __syncthreads();
    m = fmaxf(sm_[0], sm_[1]);

    float e = __expf(acc - m);
    float s = e;
#pragma unroll
    for (int d = 16; d >= 1; d >>= 1) s += __shfl_xor_sync(0xffffffffu, s, d);
    if (lane == 0) ss_[wp] = s;
    __syncthreads();
    s = ss_[0] + ss_[1];

    out[(size_t)row * TLS + t] = acc - m - __logf(s);
}

// ---------------- launch ----------------
extern "C" void kernel_launch(void* const* d_in, const int* in_sizes, int n_in,
                              void* d_out, int out_size) {
    const int*   words = (const int*)d_in[0];
    const int*   chars = (const int*)d_in[1];
    const int*   lens  = (const int*)d_in[2];
    const float* wemb  = (const float*)d_in[3];
    const float* cemb  = (const float*)d_in[4];
    const float* cWih  = (const float*)d_in[5];
    const float* cWhh  = (const float*)d_in[6];
    const float* cb    = (const float*)d_in[7];
    const float* wWih  = (const float*)d_in[8];
    const float* wWhh  = (const float*)d_in[9];
    const float* wb    = (const float*)d_in[10];
    const float* outW  = (const float*)d_in[11];
    const float* outb  = (const float*)d_in[12];
    float* out = (float*)d_out;

    init_kernel<<<4, 256>>>();
    char_lstm_kernel<<<NW / 256, 256>>>(chars, lens, cemb, cWih, cWhh, cb);
    {
        dim3 grid(G4 / BN, NW / BM);
        xp_gemm_kernel<<<grid, 256>>>(words, wemb, wWih, wb);
    }
    word_lstm_kernel<<<WBLK, WTHR>>>(wWhh);
    logits_kernel<<<NW, 64>>>(outW, outb, out);
}

// round 4
// speedup vs baseline: 1.4420x; 1.4420x over previous
#include <cuda_runtime.h>

// dims
#define NW   8192
#define LMAX 16
#define WED  506
#define WHD  512
#define G4   2048   // 4*WHD
#define CED  6
#define CHD  6
#define TLS  64

// ---------------- device scratch (no allocations allowed) ----------------
__device__ float g_hchar[NW * CHD];
__device__ float g_xp[(size_t)NW * G4];      // 64 MB
__device__ float g_hs[(size_t)NW * WHD];     // 16 MB
__device__ unsigned long long g_hbuf[2 * WHD];
__device__ unsigned long long g_flag[2 * 128];   // per-writer-block step flags

__device__ __forceinline__ float sigm(float x)  { return 1.f / (1.f + __expf(-x)); }
__device__ __forceinline__ float tanh_(float x) { return 2.f / (1.f + __expf(-2.f * x)) - 1.f; }

// ---------------- init: reset tag buffers (tags monotone within a run) ----
__global__ void init_kernel() {
    int i = blockIdx.x * blockDim.x + threadIdx.x;
    if (i < 2 * WHD) g_hbuf[i] = 0ull;       // tag=0, value=0.0f  (h_0 = 0)
    if (i < 2 * 128) g_flag[i] = 0ull;       // flag tag 0
}

// ---------------- char-level LSTM: one thread per word ----------------
__global__ void char_lstm_kernel(const int* __restrict__ chars,
                                 const int* __restrict__ lens,
                                 const float* __restrict__ cemb,   // [128,6]
                                 const float* __restrict__ cWih,   // [24,6]
                                 const float* __restrict__ cWhh,   // [24,6]
                                 const float* __restrict__ cb) {   // [24]
    __shared__ float sE[128 * CED];
    __shared__ float sWi[24 * CED];
    __shared__ float sWh[24 * CHD];
    __shared__ float sB[24];
    int tid = threadIdx.x;
    for (int i = tid; i < 128 * CED; i += blockDim.x) sE[i] = cemb[i];
    if (tid < 144) { sWi[tid] = cWih[tid]; sWh[tid] = cWhh[tid]; }
    if (tid < 24) sB[tid] = cb[tid];
    __syncthreads();

    int n = blockIdx.x * blockDim.x + tid;
    if (n >= NW) return;
    int len = lens[n];
    float h[CHD], cs[CHD];
#pragma unroll
    for (int i = 0; i < CHD; i++) { h[i] = 0.f; cs[i] = 0.f; }

    for (int l = 0; l < len; l++) {
        int ch = chars[n * LMAX + l];
        const float* e = &sE[ch * CED];
        float x0 = e[0], x1 = e[1], x2 = e[2], x3 = e[3], x4 = e[4], x5 = e[5];
        float pre[24];
#pragma unroll
        for (int gi = 0; gi < 24; gi++) {
            const float* wi = &sWi[gi * CED];
            const float* wh = &sWh[gi * CHD];
            float p = sB[gi];
            p = fmaf(wi[0], x0, p); p = fmaf(wi[1], x1, p); p = fmaf(wi[2], x2, p);
            p = fmaf(wi[3], x3, p); p = fmaf(wi[4], x4, p); p = fmaf(wi[5], x5, p);
            p = fmaf(wh[0], h[0], p); p = fmaf(wh[1], h[1], p); p = fmaf(wh[2], h[2], p);
            p = fmaf(wh[3], h[3], p); p = fmaf(wh[4], h[4], p); p = fmaf(wh[5], h[5], p);
            pre[gi] = p;
        }
#pragma unroll
        for (int hd = 0; hd < CHD; hd++) {
            float ig = sigm(pre[hd]);
            float fg = sigm(pre[CHD + hd]);
            float gg = tanh_(pre[2 * CHD + hd]);
            float og = sigm(pre[3 * CHD + hd]);
            cs[hd] = fg * cs[hd] + ig * gg;
            h[hd]  = og * tanh_(cs[hd]);
        }
    }
#pragma unroll
    for (int hd = 0; hd < CHD; hd++) g_hchar[n * CHD + hd] = h[hd];
}

// ---------------- xp GEMM: xp[n, r] = dot(x[n,:], Wih[r,:]) + b[r] ----------
#define BM 64
#define BN 64
#define BK 32
__global__ void xp_gemm_kernel(const int* __restrict__ words,
                               const float* __restrict__ wemb,   // [50000,506]
                               const float* __restrict__ Wih,    // [2048,512]
                               const float* __restrict__ wb) {   // [2048]
    __shared__ float As[BK][BM + 4];
    __shared__ float Bs[BK][BN + 4];
    __shared__ int widx[BM];

    int bn = blockIdx.x;
    int bm = blockIdx.y;
    int tid = threadIdx.x;

    if (tid < BM) widx[tid] = words[bm * BM + tid];
    __syncthreads();

    int tx = tid % 16, ty = tid / 16;
    int lm = tid % 64;
    int lk = (tid / 64) * 8;

    float acc[4][4];
#pragma unroll
    for (int i = 0; i < 4; i++)
#pragma unroll
        for (int j = 0; j < 4; j++) acc[i][j] = 0.f;

    int m_g = bm * BM + lm;
    const float* arow = wemb + (size_t)widx[lm] * WED;
    const float* brow = Wih + (size_t)(bn * BN + lm) * WHD;

    for (int k0 = 0; k0 < WHD; k0 += BK) {
#pragma unroll
        for (int q = 0; q < 8; q++) {
            int k = k0 + lk + q;
            float v = (k < WED) ? arow[k] : g_hchar[m_g * CHD + (k - WED)];
            As[lk + q][lm] = v;
            Bs[lk + q][lm] = brow[k];
        }
        __syncthreads();
#pragma unroll
        for (int k = 0; k < BK; k++) {
            float4 a = *(const float4*)&As[k][ty * 4];
            float4 b = *(const float4*)&Bs[k][tx * 4];
            acc[0][0] = fmaf(a.x, b.x, acc[0][0]); acc[0][1] = fmaf(a.x, b.y, acc[0][1]);
            acc[0][2] = fmaf(a.x, b.z, acc[0][2]); acc[0][3] = fmaf(a.x, b.w, acc[0][3]);
            acc[1][0] = fmaf(a.y, b.x, acc[1][0]); acc[1][1] = fmaf(a.y, b.y, acc[1][1]);
            acc[1][2] = fmaf(a.y, b.z, acc[1][2]); acc[1][3] = fmaf(a.y, b.w, acc[1][3]);
            acc[2][0] = fmaf(a.z, b.x, acc[2][0]); acc[2][1] = fmaf(a.z, b.y, acc[2][1]);
            acc[2][2] = fmaf(a.z, b.z, acc[2][2]); acc[2][3] = fmaf(a.z, b.w, acc[2][3]);
            acc[3][0] = fmaf(a.w, b.x, acc[3][0]); acc[3][1] = fmaf(a.w, b.y, acc[3][1]);
            acc[3][2] = fmaf(a.w, b.z, acc[3][2]); acc[3][3] = fmaf(a.w, b.w, acc[3][3]);
        }
        __syncthreads();
    }
#pragma unroll
    for (int i = 0; i < 4; i++) {
        int m = bm * BM + ty * 4 + i;
#pragma unroll
        for (int j = 0; j < 4; j++) {
            int n = bn * BN + tx * 4 + j;
            g_xp[(size_t)m * G4 + n] = acc[i][j] + wb[n];
        }
    }
}

// ---------------- persistent word LSTM (R1 skeleton + hierarchical poll) ----
// 128 blocks x 256 threads, co-resident. Block b owns hidden units 4b..4b+3
// (16 gate rows). Thread t: r = t>>4 (row), cg = t&15 (col group of 32 cols,
// strided by 16). Global row = (r&3)*512 + 4b + (r>>2).
// Publish: 4 tagged u64 (coalesced 32B) + one per-block flag u64 (poll hint).
// Readers spin on the 8B flag only, then load+verify the 32B tagged data.
#define WBLK 128
#define WTHR 256
__global__ void __launch_bounds__(WTHR, 1)
word_lstm_kernel(const float* __restrict__ Whh) {  // [2048,512]
    int b = blockIdx.x, t = threadIdx.x;
    int r = t >> 4, cg = t & 15;
    int jl = r >> 2, gg_ = r & 3;
    int row = gg_ * WHD + 4 * b + jl;

    float w[32];
#pragma unroll
    for (int k = 0; k < 32; k++) w[k] = Whh[(size_t)row * WHD + k * 16 + cg];

    __shared__ float h_s[WHD];
    __shared__ float rs[16];

    float cst = 0.f;  // cell state (threads 0..3 only)

    // xp prefetch: cg==0 threads carry current/next xp value for their row
    float x_cur = 0.f, x_nxt = 0.f;
    if (cg == 0) x_cur = __ldcg(&g_xp[(size_t)0 * G4 + row]);

    for (int step = 1; step <= NW; ++step) {
        // prefetch xp for next step (overlaps poll + matvec)
        if (cg == 0 && step < NW) x_nxt = __ldcg(&g_xp[(size_t)step * G4 + row]);

        if (t < 128) {
            unsigned long long tg = (unsigned long long)(step - 1);
            int par = (step - 1) & 1;
            // phase 1: spin on the single 8B per-writer-block flag
            volatile unsigned long long* fl = g_flag + par * 128 + t;
            while (*fl != tg) {}
            // phase 2: load tagged data, verify tags (normally 1 iteration)
            volatile unsigned long long* src = g_hbuf + par * WHD + 4 * t;
            unsigned long long v0, v1, v2, v3;
            do {
                v0 = src[0]; v1 = src[1]; v2 = src[2]; v3 = src[3];
            } while (((v0 >> 32) != tg) | ((v1 >> 32) != tg) |
                     ((v2 >> 32) != tg) | ((v3 >> 32) != tg));
            float4 hv = make_float4(__uint_as_float((unsigned)v0),
                                    __uint_as_float((unsigned)v1),
                                    __uint_as_float((unsigned)v2),
                                    __uint_as_float((unsigned)v3));
            *(float4*)&h_s[4 * t] = hv;
        }
        __syncthreads();   // S1: h_s ready

        // matvec: 4 independent FMA chains of 8 (serial latency ~45 cyc)
        float a0 = 0.f, a1 = 0.f, a2 = 0.f, a3 = 0.f;
#pragma unroll
        for (int k = 0; k < 8; k++) {
            a0 = fmaf(w[k],      h_s[k * 16 + cg],        a0);
            a1 = fmaf(w[8 + k],  h_s[(8 + k) * 16 + cg],  a1);
            a2 = fmaf(w[16 + k], h_s[(16 + k) * 16 + cg], a2);
            a3 = fmaf(w[24 + k], h_s[(24 + k) * 16 + cg], a3);
        }
        float acc = (a0 + a1) + (a2 + a3);
#pragma unroll
        for (int d = 8; d >= 1; d >>= 1)
            acc += __shfl_down_sync(0xffffffffu, acc, d, 16);
        if (cg == 0) rs[r] = acc + x_cur;
        __syncthreads();   // S2: rs ready

        // gate tail: 16 lanes of warp 0 compute nonlinearities in parallel
        if (t < 16) {
            float pre = rs[t];
            float nl = ((t & 3) == 2) ? tanh_(pre) : sigm(pre);
            float gi = __shfl_sync(0xffffu, nl, (4 * t + 0) & 15);
            float gf = __shfl_sync(0xffffu, nl, (4 * t + 1) & 15);
            float gv = __shfl_sync(0xffffu, nl, (4 * t + 2) & 15);
            float go = __shfl_sync(0xffffu, nl, (4 * t + 3) & 15);
            if (t < 4) {
                float ig = sigm(0.f), dummy; (void)ig; (void)dummy; // (no-op guard removal)
                cst = gf * cst + gi * gv;
                float h = go * tanh_(cst);
                int jj = 4 * b + t;
                g_hs[(size_t)(step - 1) * WHD + jj] = h;
                unsigned long long pk =
                    ((unsigned long long)step << 32) |
                    (unsigned long long)__float_as_uint(h);
                ((volatile unsigned long long*)g_hbuf)[(step & 1) * WHD + jj] = pk;
            }
            if (t == 0)
                ((volatile unsigned long long*)g_flag)[(step & 1) * 128 + b] =
                    (unsigned long long)step;
        }
        if (cg == 0) x_cur = x_nxt;
        // no third barrier: next S1 orders rs/h_s reuse (same as R1)
    }
}

// ---------------- logits + log_softmax: one block (64 threads) per row ----
__global__ void logits_kernel(const float* __restrict__ outW,  // [64,512]
                              const float* __restrict__ outb,  // [64]
                              float* __restrict__ out) {       // [8192,64]
    int row = blockIdx.x;
    int t = threadIdx.x;          // 0..63 (tag)
    __shared__ float h_s[WHD];
    __shared__ float sm_[2], ss_[2];

    for (int i = t; i < WHD; i += 64) h_s[i] = g_hs[(size_t)row * WHD + i];
    __syncthreads();

    float acc = outb[t];
    const float4* w4 = (const float4*)(outW + (size_t)t * WHD);
#pragma unroll 8
    for (int k4 = 0; k4 < WHD / 4; k4++) {
        float4 wv = __ldg(&w4[k4]);
        acc = fmaf(wv.x, h_s[k4 * 4 + 0], acc);
        acc = fmaf(wv.y, h_s[k4 * 4 + 1], acc);
        acc = fmaf(wv.z, h_s[k4 * 4 + 2], acc);
        acc = fmaf(wv.w, h_s[k4 * 4 + 3], acc);
    }
    int lane = t & 31, wp = t >> 5;
    float m = acc;
#pragma unroll
    for (int d = 16; d >= 1; d >>= 1) m = fmaxf(m, __shfl_xor_sync(0xffffffffu, m, d));
    if (lane == 0) sm_[wp] = m;
    __syncthreads();
    m = fmaxf(sm_[0], sm_[1]);

    float e = __expf(acc - m);
    float s = e;
#pragma unroll
    for (int d = 16; d >= 1; d >>= 1) s += __shfl_xor_sync(0xffffffffu, s, d);
    if (lane == 0) ss_[wp] = s;
    __syncthreads();
    s = ss_[0] + ss_[1];

    out[(size_t)row * TLS + t] = acc - m - __logf(s);
}

// ---------------- launch ----------------
extern "C" void kernel_launch(void* const* d_in, const int* in_sizes, int n_in,
                              void* d_out, int out_size) {
    const int*   words = (const int*)d_in[0];
    const int*   chars = (const int*)d_in[1];
    const int*   lens  = (const int*)d_in[2];
    const float* wemb  = (const float*)d_in[3];
    const float* cemb  = (const float*)d_in[4];
    const float* cWih  = (const float*)d_in[5];
    const float* cWhh  = (const float*)d_in[6];
    const float* cb    = (const float*)d_in[7];
    const float* wWih  = (const float*)d_in[8];
    const float* wWhh  = (const float*)d_in[9];
    const float* wb    = (const float*)d_in[10];
    const float* outW  = (const float*)d_in[11];
    const float* outb  = (const float*)d_in[12];
    float* out = (float*)d_out;

    init_kernel<<<4, 256>>>();
    char_lstm_kernel<<<NW / 256, 256>>>(chars, lens, cemb, cWih, cWhh, cb);
    {
        dim3 grid(G4 / BN, NW / BM);
        xp_gemm_kernel<<<grid, 256>>>(words, wemb, wWih, wb);
    }
    word_lstm_kernel<<<WBLK, WTHR>>>(wWhh);
    logits_kernel<<<NW, 64>>>(outW, outb, out);
}

// round 5
// speedup vs baseline: 2.4026x; 1.6661x over previous
#include <cuda_runtime.h>

// dims
#define NW   8192
#define LMAX 16
#define WED  506
#define WHD  512
#define G4   2048   // 4*WHD
#define CED  6
#define CHD  6
#define TLS  64

// ---------------- device scratch (no allocations allowed) ----------------
__device__ float g_hchar[NW * CHD];
__device__ float g_xp[(size_t)NW * G4];      // 64 MB
__device__ float g_hs[(size_t)NW * WHD];     // 16 MB
// push mailboxes: [parity][reader_block][unit]  (tag<<32 | h_bits)
__device__ unsigned long long g_mail[2u * 128u * 512u];   // 512 KB

__device__ __forceinline__ float sigm(float x)  { return 1.f / (1.f + __expf(-x)); }
__device__ __forceinline__ float tanh_(float x) { return 2.f / (1.f + __expf(-2.f * x)) - 1.f; }

// ---------------- init: zero mailboxes (tag 0 == h_0 = 0) ----------------
__global__ void init_kernel() {
    int i = blockIdx.x * blockDim.x + threadIdx.x;
    if (i < 2 * 128 * 512) g_mail[i] = 0ull;
}

// ---------------- char-level LSTM: one thread per word ----------------
__global__ void char_lstm_kernel(const int* __restrict__ chars,
                                 const int* __restrict__ lens,
                                 const float* __restrict__ cemb,   // [128,6]
                                 const float* __restrict__ cWih,   // [24,6]
                                 const float* __restrict__ cWhh,   // [24,6]
                                 const float* __restrict__ cb) {   // [24]
    __shared__ float sE[128 * CED];
    __shared__ float sWi[24 * CED];
    __shared__ float sWh[24 * CHD];
    __shared__ float sB[24];
    int tid = threadIdx.x;
    for (int i = tid; i < 128 * CED; i += blockDim.x) sE[i] = cemb[i];
    if (tid < 144) { sWi[tid] = cWih[tid]; sWh[tid] = cWhh[tid]; }
    if (tid < 24) sB[tid] = cb[tid];
    __syncthreads();

    int n = blockIdx.x * blockDim.x + tid;
    if (n >= NW) return;
    int len = lens[n];
    float h[CHD], cs[CHD];
#pragma unroll
    for (int i = 0; i < CHD; i++) { h[i] = 0.f; cs[i] = 0.f; }

    for (int l = 0; l < len; l++) {
        int ch = chars[n * LMAX + l];
        const float* e = &sE[ch * CED];
        float x0 = e[0], x1 = e[1], x2 = e[2], x3 = e[3], x4 = e[4], x5 = e[5];
        float pre[24];
#pragma unroll
        for (int gi = 0; gi < 24; gi++) {
            const float* wi = &sWi[gi * CED];
            const float* wh = &sWh[gi * CHD];
            float p = sB[gi];
            p = fmaf(wi[0], x0, p); p = fmaf(wi[1], x1, p); p = fmaf(wi[2], x2, p);
            p = fmaf(wi[3], x3, p); p = fmaf(wi[4], x4, p); p = fmaf(wi[5], x5, p);
            p = fmaf(wh[0], h[0], p); p = fmaf(wh[1], h[1], p); p = fmaf(wh[2], h[2], p);
            p = fmaf(wh[3], h[3], p); p = fmaf(wh[4], h[4], p); p = fmaf(wh[5], h[5], p);
            pre[gi] = p;
        }
#pragma unroll
        for (int hd = 0; hd < CHD; hd++) {
            float ig = sigm(pre[hd]);
            float fg = sigm(pre[CHD + hd]);
            float gg = tanh_(pre[2 * CHD + hd]);
            float og = sigm(pre[3 * CHD + hd]);
            cs[hd] = fg * cs[hd] + ig * gg;
            h[hd]  = og * tanh_(cs[hd]);
        }
    }
#pragma unroll
    for (int hd = 0; hd < CHD; hd++) g_hchar[n * CHD + hd] = h[hd];
}

// ---------------- xp GEMM: xp[n, r] = dot(x[n,:], Wih[r,:]) + b[r] ----------
#define BM 64
#define BN 64
#define BK 32
__global__ void xp_gemm_kernel(const int* __restrict__ words,
                               const float* __restrict__ wemb,   // [50000,506]
                               const float* __restrict__ Wih,    // [2048,512]
                               const float* __restrict__ wb) {   // [2048]
    __shared__ float As[BK][BM + 4];
    __shared__ float Bs[BK][BN + 4];
    __shared__ int widx[BM];

    int bn = blockIdx.x;
    int bm = blockIdx.y;
    int tid = threadIdx.x;

    if (tid < BM) widx[tid] = words[bm * BM + tid];
    __syncthreads();

    int tx = tid % 16, ty = tid / 16;
    int lm = tid % 64;
    int lk = (tid / 64) * 8;

    float acc[4][4];
#pragma unroll
    for (int i = 0; i < 4; i++)
#pragma unroll
        for (int j = 0; j < 4; j++) acc[i][j] = 0.f;

    int m_g = bm * BM + lm;
    const float* arow = wemb + (size_t)widx[lm] * WED;
    const float* brow = Wih + (size_t)(bn * BN + lm) * WHD;

    for (int k0 = 0; k0 < WHD; k0 += BK) {
#pragma unroll
        for (int q = 0; q < 8; q++) {
            int k = k0 + lk + q;
            float v = (k < WED) ? arow[k] : g_hchar[m_g * CHD + (k - WED)];
            As[lk + q][lm] = v;
            Bs[lk + q][lm] = brow[k];
        }
        __syncthreads();
#pragma unroll
        for (int k = 0; k < BK; k++) {
            float4 a = *(const float4*)&As[k][ty * 4];
            float4 b = *(const float4*)&Bs[k][tx * 4];
            acc[0][0] = fmaf(a.x, b.x, acc[0][0]); acc[0][1] = fmaf(a.x, b.y, acc[0][1]);
            acc[0][2] = fmaf(a.x, b.z, acc[0][2]); acc[0][3] = fmaf(a.x, b.w, acc[0][3]);
            acc[1][0] = fmaf(a.y, b.x, acc[1][0]); acc[1][1] = fmaf(a.y, b.y, acc[1][1]);
            acc[1][2] = fmaf(a.y, b.z, acc[1][2]); acc[1][3] = fmaf(a.y, b.w, acc[1][3]);
            acc[2][0] = fmaf(a.z, b.x, acc[2][0]); acc[2][1] = fmaf(a.z, b.y, acc[2][1]);
            acc[2][2] = fmaf(a.z, b.z, acc[2][2]); acc[2][3] = fmaf(a.z, b.w, acc[2][3]);
            acc[3][0] = fmaf(a.w, b.x, acc[3][0]); acc[3][1] = fmaf(a.w, b.y, acc[3][1]);
            acc[3][2] = fmaf(a.w, b.z, acc[3][2]); acc[3][3] = fmaf(a.w, b.w, acc[3][3]);
        }
        __syncthreads();
    }
#pragma unroll
    for (int i = 0; i < 4; i++) {
        int m = bm * BM + ty * 4 + i;
#pragma unroll
        for (int j = 0; j < 4; j++) {
            int n = bn * BN + tx * 4 + j;
            g_xp[(size_t)m * G4 + n] = acc[i][j] + wb[n];
        }
    }
}

// ---------------- persistent word LSTM (push mailboxes) ----------------
// 128 blocks x 256 threads, co-resident. Block b owns hidden units 4b..4b+3.
// Thread t: r = t>>4 (gate row 0..15), cg = t&15; global row = (r&3)*512+4b+(r>>2).
// Sync: writers PUSH 4 tagged u64 into every reader's private mailbox
// (mail[par][reader][unit]); reader thread t spins on its OWN 32B sector
// mail[par][b][4t..4t+3] -> no L2 slice hot-spotting. Tag-in-word (step) with
// parity double buffering; 16B v2.u64 stores commit atomically.
#define WBLK 128
#define WTHR 256
__global__ void __launch_bounds__(WTHR, 1)
word_lstm_kernel(const float* __restrict__ Whh) {  // [2048,512]
    int b = blockIdx.x, t = threadIdx.x;
    int r = t >> 4, cg = t & 15;
    int jl = r >> 2, gg_ = r & 3;
    int row = gg_ * WHD + 4 * b + jl;

    float w[32];
#pragma unroll
    for (int k = 0; k < 32; k++) w[k] = Whh[(size_t)row * WHD + k * 16 + cg];

    __shared__ float h_s[WHD];
    __shared__ float rs[16];

    float cst = 0.f;  // cell state (lanes 0..3 of warp 0)

    // xp prefetch: cg==0 threads carry current/next xp for their row
    float x_cur = 0.f, x_nxt = 0.f;
    if (cg == 0) x_cur = __ldcg(&g_xp[row]);

    for (int step = 1; step <= NW; ++step) {
        if (cg == 0 && step < NW) x_nxt = __ldcg(&g_xp[(size_t)step * G4 + row]);

        // ---- poll own mailbox sector (private: no slice contention) ----
        if (t < 128) {
            unsigned long long tg = (unsigned long long)(step - 1);
            volatile unsigned long long* src =
                g_mail + (((size_t)((step - 1) & 1) * 128 + (size_t)b) << 9) + 4 * t;
            unsigned long long v0, v1, v2, v3;
            do {
                v0 = src[0]; v1 = src[1]; v2 = src[2]; v3 = src[3];
            } while (((v0 >> 32) != tg) | ((v1 >> 32) != tg) |
                     ((v2 >> 32) != tg) | ((v3 >> 32) != tg));
            float4 hv = make_float4(__uint_as_float((unsigned)v0),
                                    __uint_as_float((unsigned)v1),
                                    __uint_as_float((unsigned)v2),
                                    __uint_as_float((unsigned)v3));
            *(float4*)&h_s[4 * t] = hv;
        }
        __syncthreads();   // S1: h_s ready

        // ---- matvec: 4 independent FMA chains of 8 ----
        float a0 = 0.f, a1 = 0.f, a2 = 0.f, a3 = 0.f;
#pragma unroll
        for (int k = 0; k < 8; k++) {
            a0 = fmaf(w[k],      h_s[k * 16 + cg],        a0);
            a1 = fmaf(w[8 + k],  h_s[(8 + k) * 16 + cg],  a1);
            a2 = fmaf(w[16 + k], h_s[(16 + k) * 16 + cg], a2);
            a3 = fmaf(w[24 + k], h_s[(24 + k) * 16 + cg], a3);
        }
        float acc = (a0 + a1) + (a2 + a3);
#pragma unroll
        for (int d = 8; d >= 1; d >>= 1)
            acc += __shfl_down_sync(0xffffffffu, acc, d, 16);
        if (cg == 0) rs[r] = acc + x_cur;
        __syncthreads();   // S2: rs ready

        // ---- gate tail + push (warp 0 only) ----
        if (t < 32) {
            float nl = 0.f;
            if (t < 16) {
                float pre = rs[t];
                nl = ((t & 3) == 2) ? tanh_(pre) : sigm(pre);
            }
            int uu = t & 3;
            float gi = __shfl_sync(0xffffffffu, nl, 4 * uu + 0);
            float gf = __shfl_sync(0xffffffffu, nl, 4 * uu + 1);
            float gv = __shfl_sync(0xffffffffu, nl, 4 * uu + 2);
            float go = __shfl_sync(0xffffffffu, nl, 4 * uu + 3);
            float hval = 0.f;
            if (t < 4) {
                cst = gf * cst + gi * gv;
                hval = go * tanh_(cst);
                g_hs[(size_t)(step - 1) * WHD + 4 * b + t] = hval;
            }
            // broadcast the 4 h values to all 32 lanes
            float h0 = __shfl_sync(0xffffffffu, hval, 0);
            float h1 = __shfl_sync(0xffffffffu, hval, 1);
            float h2 = __shfl_sync(0xffffffffu, hval, 2);
            float h3 = __shfl_sync(0xffffffffu, hval, 3);
            unsigned long long hi = ((unsigned long long)step) << 32;
            unsigned long long pk0 = hi | (unsigned long long)__float_as_uint(h0);
            unsigned long long pk1 = hi | (unsigned long long)__float_as_uint(h1);
            unsigned long long pk2 = hi | (unsigned long long)__float_as_uint(h2);
            unsigned long long pk3 = hi | (unsigned long long)__float_as_uint(h3);
            // push to 4 readers per lane: mail[step&1][rdr][4b..4b+3]
            unsigned long long* base =
                g_mail + (((size_t)(step & 1) * 128) << 9) + 4 * b;
#pragma unroll
            for (int q = 0; q < 4; q++) {
                unsigned long long* d = base + ((size_t)(4 * t + q) << 9);
                asm volatile("st.global.v2.u64 [%0], {%1,%2};"
                             :: "l"(d), "l"(pk0), "l"(pk1) : "memory");
                asm volatile("st.global.v2.u64 [%0+16], {%1,%2};"
                             :: "l"(d), "l"(pk2), "l"(pk3) : "memory");
            }
        }
        if (cg == 0) x_cur = x_nxt;
        // no third barrier: next S1/S2 order rs/h_s reuse (same as R1)
    }
}

// ---------------- logits + log_softmax: one block (64 threads) per row ----
__global__ void logits_kernel(const float* __restrict__ outW,  // [64,512]
                              const float* __restrict__ outb,  // [64]
                              float* __restrict__ out) {       // [8192,64]
    int row = blockIdx.x;
    int t = threadIdx.x;          // 0..63
    __shared__ float h_s[WHD];
    __shared__ float sm_[2], ss_[2];

    for (int i = t; i < WHD; i += 64) h_s[i] = g_hs[(size_t)row * WHD + i];
    __syncthreads();

    float acc = outb[t];
    const float4* w4 = (const float4*)(outW + (size_t)t * WHD);
#pragma unroll 8
    for (int k4 = 0; k4 < WHD / 4; k4++) {
        float4 wv = __ldg(&w4[k4]);
        acc = fmaf(wv.x, h_s[k4 * 4 + 0], acc);
        acc = fmaf(wv.y, h_s[k4 * 4 + 1], acc);
        acc = fmaf(wv.z, h_s[k4 * 4 + 2], acc);
        acc = fmaf(wv.w, h_s[k4 * 4 + 3], acc);
    }
    int lane = t & 31, wp = t >> 5;
    float m = acc;
#pragma unroll
    for (int d = 16; d >= 1; d >>= 1) m = fmaxf(m, __shfl_xor_sync(0xffffffffu, m, d));
    if (lane == 0) sm_[wp] = m;
    __syncthreads();
    m = fmaxf(sm_[0], sm_[1]);

    float e = __expf(acc - m);
    float s = e;
#pragma unroll
    for (int d = 16; d >= 1; d >>= 1) s += __shfl_xor_sync(0xffffffffu, s, d);
    if (lane == 0) ss_[wp] = s;
    __syncthreads();
    s = ss_[0] + ss_[1];

    out[(size_t)row * TLS + t] = acc - m - __logf(s);
}

// ---------------- launch ----------------
extern "C" void kernel_launch(void* const* d_in, const int* in_sizes, int n_in,
                              void* d_out, int out_size) {
    const int*   words = (const int*)d_in[0];
    const int*   chars = (const int*)d_in[1];
    const int*   lens  = (const int*)d_in[2];
    const float* wemb  = (const float*)d_in[3];
    const float* cemb  = (const float*)d_in[4];
    const float* cWih  = (const float*)d_in[5];
    const float* cWhh  = (const float*)d_in[6];
    const float* cb    = (const float*)d_in[7];
    const float* wWih  = (const float*)d_in[8];
    const float* wWhh  = (const float*)d_in[9];
    const float* wb    = (const float*)d_in[10];
    const float* outW  = (const float*)d_in[11];
    const float* outb  = (const float*)d_in[12];
    float* out = (float*)d_out;

    init_kernel<<<512, 256>>>();
    char_lstm_kernel<<<NW / 256, 256>>>(chars, lens, cemb, cWih, cWhh, cb);
    {
        dim3 grid(G4 / BN, NW / BM);
        xp_gemm_kernel<<<grid, 256>>>(words, wemb, wWih, wb);
    }
    word_lstm_kernel<<<WBLK, WTHR>>>(wWhh);
    logits_kernel<<<NW, 64>>>(outW, outb, out);
}